// round 4
// baseline (speedup 1.0000x reference)
#include <cuda_runtime.h>
#include <cuda_fp16.h>
#include <cstdint>

// Problem constants
#define NN 100000   // nodes
#define NH 50000    // hyperedges
#define NI 600000   // incidences
#define DH 128
#define NC 40

// ---------------- scratch (device globals) -----------------------------------
__device__ __align__(128) float  g_x0  [NN * DH];
__device__ __align__(128) float  g_x1  [NH * DH];
__device__ __align__(128) __half g_m0h [NN * DH];
__device__ __align__(128) float  g_m0he[NH * DH];
__device__ __align__(128) __half g_m1h [NH * DH];
__device__ __align__(128) float  g_m1n [NN * DH];
__device__ __align__(128) __half g_wt  [131072];   // transposed fp16 weights

#define WT_ENC  0          // 128 x 256
#define WT_MSG0 32768      // 2 x (128 x 128)
#define WT_MSG1 65536      // 2 x (128 x 256)

__device__ __forceinline__ float sigm(float x) {
    return 1.0f / (1.0f + __expf(-x));
}

__device__ __forceinline__ void mma_f16(float (&d)[4], const uint32_t (&a)[4],
                                        const uint32_t (&b)[2]) {
    asm volatile(
        "mma.sync.aligned.m16n8k16.row.col.f32.f16.f16.f32 "
        "{%0,%1,%2,%3}, {%4,%5,%6,%7}, {%8,%9}, {%0,%1,%2,%3};"
        : "+f"(d[0]), "+f"(d[1]), "+f"(d[2]), "+f"(d[3])
        : "r"(a[0]), "r"(a[1]), "r"(a[2]), "r"(a[3]), "r"(b[0]), "r"(b[1]));
}

__device__ __forceinline__ void ldsm4(uint32_t (&r)[4], uint32_t addr) {
    asm volatile("ldmatrix.sync.aligned.m8n8.x4.shared.b16 {%0,%1,%2,%3}, [%4];"
        : "=r"(r[0]), "=r"(r[1]), "=r"(r[2]), "=r"(r[3]) : "r"(addr));
}

__device__ __forceinline__ void cp16(uint32_t dst, const void* src) {
    asm volatile("cp.async.cg.shared.global [%0], [%1], 16;"
                 :: "r"(dst), "l"(src));
}

// SMEM geometry: 3 stages, A and B tiles 128 rows x 32 halves, row stride 40 halves
#define STAGES 3
#define ASTR 40
#define STAGE_B (128 * ASTR * 2)            // 10240 bytes
#define SMEM_BYTES (STAGES * 2 * STAGE_B)   // 61440 bytes

// ---------------- fp16 tensor-core GEMM:  C[M,128] = A[M,KTOT] @ Wt^T + bias
// A fp32 in gmem (two 128-col pieces A0/A1, or FUSE: sigm(A0+A1) with writeback).
// Wt fp16 [128 n][KTOT k] (pre-transposed weights), loaded via cp.async.
// Block 128x128, 256 threads (8 warps 4x2), warp tile 32x64, 3-stage pipeline.
template<int KTOT, bool SIG, bool FUSE, bool OUTH>
__global__ __launch_bounds__(256, 2)
void gemm_tc(const float* __restrict__ A0, int lda0,
             const float* __restrict__ A1, int lda1,
             float* __restrict__ Awb,
             const __half* __restrict__ Wt,
             const float* __restrict__ bias,
             float* __restrict__ C, int M)
{
    extern __shared__ __half smem[];
    uint32_t smem_u32;
    asm("{ .reg .u64 t; cvta.to.shared.u64 t, %1; cvt.u32.u64 %0, t; }"
        : "=r"(smem_u32) : "l"(smem));
    const uint32_t as0 = smem_u32;
    const uint32_t bs0 = smem_u32 + STAGES * STAGE_B;

    const int tid  = threadIdx.x;
    const int lane = tid & 31;
    const int wid  = tid >> 5;
    const int wm   = wid & 3;
    const int wn   = wid >> 2;
    const int block_row = blockIdx.x * 128;
    constexpr int NCHUNK = KTOT / 32;

    // A loader mapping: thread -> (row, 16-half k segment)
    const int arow = tid >> 1;
    const int aseg = tid & 1;
    const int grow = block_row + arow;

    // ldmatrix lane mappings
    const int arow_f = ((lane >> 3) & 1) * 8 + (lane & 7);
    const int akk_f  = (lane >> 4) * 8;
    const int brow_f = (lane >> 4) * 8 + (lane & 7);
    const int bkk_f  = ((lane >> 3) & 1) * 8;

    uint32_t aaddr[2], baddr[4];
    #pragma unroll
    for (int mi = 0; mi < 2; mi++)
        aaddr[mi] = as0 + ((wm * 32 + mi * 16 + arow_f) * ASTR + akk_f) * 2;
    #pragma unroll
    for (int nj = 0; nj < 4; nj++)
        baddr[nj] = bs0 + ((wn * 64 + nj * 16 + brow_f) * ASTR + bkk_f) * 2;

    float acc[2][8][4];
    #pragma unroll
    for (int mi = 0; mi < 2; mi++)
        #pragma unroll
        for (int ni = 0; ni < 8; ni++)
            #pragma unroll
            for (int j = 0; j < 4; j++) acc[mi][ni][j] = 0.0f;

    float4 pa[4], pb[4];

    auto ldgA = [&](int c) {
        const int gcol = c * 32 + aseg * 16;
        if (grow < M) {
            const float* base;
            int col;
            if (!FUSE) {
                if (gcol < 128) { base = A0 + (size_t)grow * lda0; col = gcol; }
                else            { base = A1 + (size_t)grow * lda1; col = gcol - 128; }
            } else { base = A0 + (size_t)grow * lda0; col = gcol; }
            #pragma unroll
            for (int j = 0; j < 4; j++) pa[j] = *(const float4*)(base + col + 4 * j);
            if (FUSE) {
                const float* b2 = A1 + (size_t)grow * lda1 + gcol;
                #pragma unroll
                for (int j = 0; j < 4; j++) pb[j] = *(const float4*)(b2 + 4 * j);
            }
        } else {
            #pragma unroll
            for (int j = 0; j < 4; j++) pa[j] = make_float4(0.f, 0.f, 0.f, 0.f);
            if (FUSE) {
                #pragma unroll
                for (int j = 0; j < 4; j++) pb[j] = make_float4(0.f, 0.f, 0.f, 0.f);
            }
        }
    };

    auto stsA = [&](int c, int s) {
        const int gcol = c * 32 + aseg * 16;
        float4 v[4];
        #pragma unroll
        for (int j = 0; j < 4; j++) {
            v[j] = pa[j];
            if (FUSE) {
                v[j].x = sigm(v[j].x + pb[j].x);
                v[j].y = sigm(v[j].y + pb[j].y);
                v[j].z = sigm(v[j].z + pb[j].z);
                v[j].w = sigm(v[j].w + pb[j].w);
            }
        }
        if (FUSE && grow < M) {
            #pragma unroll
            for (int j = 0; j < 4; j++)
                *(float4*)(Awb + (size_t)grow * 128 + gcol + 4 * j) = v[j];
        }
        uint32_t h[8];
        #pragma unroll
        for (int j = 0; j < 4; j++) {
            __half2 h0 = __floats2half2_rn(v[j].x, v[j].y);
            __half2 h1 = __floats2half2_rn(v[j].z, v[j].w);
            h[2 * j]     = *reinterpret_cast<uint32_t*>(&h0);
            h[2 * j + 1] = *reinterpret_cast<uint32_t*>(&h1);
        }
        const uint32_t dst = as0 + s * STAGE_B + (arow * ASTR + aseg * 16) * 2;
        asm volatile("st.shared.v4.b32 [%0], {%1,%2,%3,%4};"
                     :: "r"(dst), "r"(h[0]), "r"(h[1]), "r"(h[2]), "r"(h[3]));
        asm volatile("st.shared.v4.b32 [%0], {%1,%2,%3,%4};"
                     :: "r"(dst + 16), "r"(h[4]), "r"(h[5]), "r"(h[6]), "r"(h[7]));
    };

    auto cpB = [&](int c, int s) {
        const int k0 = c * 32;
        #pragma unroll
        for (int i = 0; i < 2; i++) {
            const int idx = tid + i * 256;
            const int row = idx >> 2;
            const int seg = idx & 3;
            const uint32_t dst = bs0 + s * STAGE_B + (row * ASTR + seg * 8) * 2;
            cp16(dst, Wt + (size_t)row * KTOT + k0 + seg * 8);
        }
    };

    ldgA(0);
    cpB(0, 0);
    asm volatile("cp.async.commit_group;");

    for (int c = 0; c < NCHUNK; c++) {
        const int s = c % 3;
        stsA(c, s);
        if (c + 1 < NCHUNK) {
            ldgA(c + 1);
            cpB(c + 1, (c + 1) % 3);
            asm volatile("cp.async.commit_group;");
            asm volatile("cp.async.wait_group 1;");
        } else {
            asm volatile("cp.async.wait_group 0;");
        }
        __syncthreads();

        #pragma unroll
        for (int ks = 0; ks < 2; ks++) {
            const uint32_t koff = s * STAGE_B + ks * 32;
            uint32_t af[2][4];
            ldsm4(af[0], aaddr[0] + koff);
            ldsm4(af[1], aaddr[1] + koff);
            uint32_t bf[4][4];
            #pragma unroll
            for (int nj = 0; nj < 4; nj++) ldsm4(bf[nj], baddr[nj] + koff);
            #pragma unroll
            for (int mi = 0; mi < 2; mi++)
                #pragma unroll
                for (int ni = 0; ni < 8; ni++) {
                    uint32_t b[2] = { bf[ni >> 1][(ni & 1) * 2],
                                      bf[ni >> 1][(ni & 1) * 2 + 1] };
                    mma_f16(acc[mi][ni], af[mi], b);
                }
        }
        __syncthreads();
    }

    // ---- epilogue ----
    const int lr = lane >> 2, lc = lane & 3;
    #pragma unroll
    for (int mi = 0; mi < 2; mi++) {
        const int r0 = block_row + wm * 32 + mi * 16 + lr;
        #pragma unroll
        for (int ni = 0; ni < 8; ni++) {
            const int col = wn * 64 + ni * 8 + 2 * lc;
            const float b0 = bias[col], b1 = bias[col + 1];
            float v0 = acc[mi][ni][0] + b0;
            float v1 = acc[mi][ni][1] + b1;
            float v2 = acc[mi][ni][2] + b0;
            float v3 = acc[mi][ni][3] + b1;
            if (SIG) { v0 = sigm(v0); v1 = sigm(v1); v2 = sigm(v2); v3 = sigm(v3); }
            if (OUTH) {
                __half* C16 = (__half*)C;
                __half2 h01 = __floats2half2_rn(v0, v1);
                __half2 h23 = __floats2half2_rn(v2, v3);
                if (r0 < M)     *(__half2*)(C16 + (size_t)r0 * 128 + col) = h01;
                if (r0 + 8 < M) *(__half2*)(C16 + (size_t)(r0 + 8) * 128 + col) = h23;
            } else {
                if (r0 < M)
                    *(float2*)(C + (size_t)r0 * 128 + col) = make_float2(v0, v1);
                if (r0 + 8 < M)
                    *(float2*)(C + (size_t)(r0 + 8) * 128 + col) = make_float2(v2, v3);
            }
        }
    }
}

// ---------------- weight transpose+convert: Wt[n][k] = (half)W[k][n] ---------
__global__ void wtrans(const float* __restrict__ W, __half* __restrict__ Wt, int K)
{
    __shared__ float tile[32][33];
    const int kb = blockIdx.x * 32, nb = blockIdx.y * 32;
    const int tx = threadIdx.x, ty = threadIdx.y;
    #pragma unroll
    for (int i = 0; i < 32; i += 8)
        tile[ty + i][tx] = W[(size_t)(kb + ty + i) * 128 + nb + tx];
    __syncthreads();
    #pragma unroll
    for (int i = 0; i < 32; i += 8)
        Wt[(size_t)(nb + ty + i) * K + kb + tx] = __float2half(tile[tx][ty + i]);
}

// ---------------- output GEMM: C[M,40] = sigm(A+Mx) @ W[128,40] + bias -------
__global__ __launch_bounds__(256)
void gemm_out(const float* __restrict__ A, const float* __restrict__ Mx,
              const float* __restrict__ W,
              const float* __restrict__ bias, float* __restrict__ C, int M)
{
    __shared__ float Ws[128][40];
    __shared__ float Asm[32][132];

    const int tid = threadIdx.x;
    const int row0 = blockIdx.x * 32;

    for (int i = tid; i < 128 * 40; i += 256)
        Ws[i / 40][i % 40] = W[i];

    for (int i = tid; i < 32 * 32; i += 256) {
        int r = i >> 5, c = (i & 31) * 4;
        float4 v = make_float4(0.f, 0.f, 0.f, 0.f);
        if (row0 + r < M) {
            v = *(const float4*)(A + (size_t)(row0 + r) * 128 + c);
            const float4 m = *(const float4*)(Mx + (size_t)(row0 + r) * 128 + c);
            v.x = sigm(v.x + m.x); v.y = sigm(v.y + m.y);
            v.z = sigm(v.z + m.z); v.w = sigm(v.w + m.w);
        }
        Asm[r][c + 0] = v.x; Asm[r][c + 1] = v.y; Asm[r][c + 2] = v.z; Asm[r][c + 3] = v.w;
    }
    __syncthreads();

    const int r  = tid >> 3;
    const int c0 = (tid & 7) * 5;
    float acc[5];
    #pragma unroll
    for (int j = 0; j < 5; j++) acc[j] = bias[c0 + j];

    for (int k = 0; k < 128; k++) {
        float a = Asm[r][k];
        #pragma unroll
        for (int j = 0; j < 5; j++) acc[j] += a * Ws[k][c0 + j];
    }

    if (row0 + r < M) {
        #pragma unroll
        for (int j = 0; j < 5; j++)
            C[(size_t)(row0 + r) * 40 + c0 + j] = acc[j];
    }
}

// ---------------- edge scatter (fp16 src): dst[s[e]] += v[e]*src[g[e]] -------
__device__ __forceinline__ void red8(float* d, uint4 s, float w) {
    const __half2* hp = (const __half2*)&s;
    float2 f0 = __half22float2(hp[0]);
    float2 f1 = __half22float2(hp[1]);
    float2 f2 = __half22float2(hp[2]);
    float2 f3 = __half22float2(hp[3]);
    asm volatile("red.global.add.v4.f32 [%0], {%1,%2,%3,%4};" :: "l"(d),
        "f"(w * f0.x), "f"(w * f0.y), "f"(w * f1.x), "f"(w * f1.y) : "memory");
    asm volatile("red.global.add.v4.f32 [%0], {%1,%2,%3,%4};" :: "l"(d + 4),
        "f"(w * f2.x), "f"(w * f2.y), "f"(w * f3.x), "f"(w * f3.y) : "memory");
}

__global__ void scatter_h(const __half* __restrict__ src,
                          const int*    __restrict__ gidx,
                          const int*    __restrict__ sidx,
                          const float*  __restrict__ vals,
                          float* __restrict__ dst, int nh)
{
    const int t = blockIdx.x * blockDim.x + threadIdx.x;
    const int e = t >> 4;
    if (e >= nh) return;
    const int g  = (t & 15) << 3;
    const int e2 = e + nh;

    const float w1 = __ldg(vals + e);
    const float w2 = __ldg(vals + e2);
    const int   g1 = __ldg(gidx + e);
    const int   g2 = __ldg(gidx + e2);
    const int   s1 = __ldg(sidx + e);
    const int   s2 = __ldg(sidx + e2);
    const uint4 d1 = *(const uint4*)(src + (size_t)g1 * 128 + g);
    const uint4 d2 = *(const uint4*)(src + (size_t)g2 * 128 + g);
    red8(dst + (size_t)s1 * 128 + g, d1, w1);
    red8(dst + (size_t)s2 * 128 + g, d2, w2);
}

// ---------------- elementwise update (x = sigm(x + m)) ----------------------
__global__ void update_kernel(float4* __restrict__ x, const float4* __restrict__ m, int n4)
{
    int i = blockIdx.x * blockDim.x + threadIdx.x;
    if (i >= n4) return;
    float4 a = x[i];
    float4 b = m[i];
    a.x = sigm(a.x + b.x);
    a.y = sigm(a.y + b.y);
    a.z = sigm(a.z + b.z);
    a.w = sigm(a.w + b.w);
    x[i] = a;
}

// ---------------- host driver ------------------------------------------------
extern "C" void kernel_launch(void* const* d_in, const int* in_sizes, int n_in,
                              void* d_out, int out_size)
{
    const float* x_0      = (const float*)d_in[0];
    const float* x_1      = (const float*)d_in[1];
    const int*   node_idx = (const int*)  d_in[2];
    const int*   he_idx   = (const int*)  d_in[3];
    const float* inc_vals = (const float*)d_in[4];
    const float* W_enc    = (const float*)d_in[5];
    const float* b_enc    = (const float*)d_in[6];
    const float* W_msg0   = (const float*)d_in[7];
    const float* b_msg0   = (const float*)d_in[8];
    const float* W_msg1   = (const float*)d_in[9];
    const float* b_msg1   = (const float*)d_in[10];
    const float* W_out    = (const float*)d_in[11];
    const float* b_out    = (const float*)d_in[12];
    float* out = (float*)d_out;

    float *x0, *x1, *m0he, *m1n;
    __half *m0h, *m1h, *wt;
    cudaGetSymbolAddress((void**)&x0,   g_x0);
    cudaGetSymbolAddress((void**)&x1,   g_x1);
    cudaGetSymbolAddress((void**)&m0h,  g_m0h);
    cudaGetSymbolAddress((void**)&m0he, g_m0he);
    cudaGetSymbolAddress((void**)&m1h,  g_m1h);
    cudaGetSymbolAddress((void**)&m1n,  g_m1n);
    cudaGetSymbolAddress((void**)&wt,   g_wt);

    static int smem_set = 0;
    if (!smem_set) {
        cudaFuncSetAttribute(gemm_tc<256, false, false, false>,
                             cudaFuncAttributeMaxDynamicSharedMemorySize, SMEM_BYTES);
        cudaFuncSetAttribute(gemm_tc<128, true, false, true>,
                             cudaFuncAttributeMaxDynamicSharedMemorySize, SMEM_BYTES);
        cudaFuncSetAttribute(gemm_tc<256, true, false, true>,
                             cudaFuncAttributeMaxDynamicSharedMemorySize, SMEM_BYTES);
        cudaFuncSetAttribute(gemm_tc<128, true, true, true>,
                             cudaFuncAttributeMaxDynamicSharedMemorySize, SMEM_BYTES);
        smem_set = 1;
    }

    const int gNN = (NN + 127) / 128;
    const int gNH = (NH + 127) / 128;
    const int scatter_blocks = (NI / 2) * 16 / 256;   // 18750

    // weight transpose + fp16 convert
    wtrans<<<dim3(8, 4), dim3(32, 8)>>>(W_enc,           wt + WT_ENC,           256);
    wtrans<<<dim3(4, 4), dim3(32, 8)>>>(W_msg0,          wt + WT_MSG0,          128);
    wtrans<<<dim3(4, 4), dim3(32, 8)>>>(W_msg0 + 16384,  wt + WT_MSG0 + 16384,  128);
    wtrans<<<dim3(8, 4), dim3(32, 8)>>>(W_msg1,          wt + WT_MSG1,          256);
    wtrans<<<dim3(8, 4), dim3(32, 8)>>>(W_msg1 + 32768,  wt + WT_MSG1 + 32768,  256);

    // encode
    gemm_tc<256, false, false, false><<<gNN, 256, SMEM_BYTES>>>(
        x_0, 256, x_0 + 128, 256, nullptr, wt + WT_ENC, b_enc, x0, NN);
    gemm_tc<256, false, false, false><<<gNH, 256, SMEM_BYTES>>>(
        x_1, 256, x_1 + 128, 256, nullptr, wt + WT_ENC, b_enc, x1, NH);

    // ---------------- layer 0 ----------------
    gemm_tc<128, true, false, true><<<gNN, 256, SMEM_BYTES>>>(
        x0, 128, x0, 128, nullptr, wt + WT_MSG0, b_msg0, (float*)m0h, NN);
    cudaMemsetAsync(m0he, 0, (size_t)NH * DH * sizeof(float));
    scatter_h<<<scatter_blocks, 256>>>(m0h, node_idx, he_idx, inc_vals, m0he, NI / 2);

    gemm_tc<256, true, false, true><<<gNH, 256, SMEM_BYTES>>>(
        x1, 128, m0he, 128, nullptr, wt + WT_MSG1, b_msg1, (float*)m1h, NH);
    cudaMemsetAsync(m1n, 0, (size_t)NN * DH * sizeof(float));
    scatter_h<<<scatter_blocks, 256>>>(m1h, he_idx, node_idx, inc_vals, m1n, NI / 2);

    // x1 = sigm(x1 + m0he)  (needed before m0he is overwritten)
    update_kernel<<<(NH * DH / 4 + 255) / 256, 256>>>(
        (float4*)x1, (const float4*)m0he, NH * DH / 4);

    // ---------------- layer 1 ----------------
    // m0 = sigm( sigm(x0+m1n) @ W ); writes back x0 <- sigm(x0+m1n)
    gemm_tc<128, true, true, true><<<gNN, 256, SMEM_BYTES>>>(
        x0, 128, m1n, 128, x0, wt + WT_MSG0 + 16384, b_msg0 + 128, (float*)m0h, NN);
    cudaMemsetAsync(m0he, 0, (size_t)NH * DH * sizeof(float));
    scatter_h<<<scatter_blocks, 256>>>(m0h, node_idx, he_idx, inc_vals, m0he, NI / 2);

    gemm_tc<256, true, false, true><<<gNH, 256, SMEM_BYTES>>>(
        x1, 128, m0he, 128, nullptr, wt + WT_MSG1 + 32768, b_msg1 + 128, (float*)m1h, NH);
    cudaMemsetAsync(m1n, 0, (size_t)NN * DH * sizeof(float));
    scatter_h<<<scatter_blocks, 256>>>(m1h, he_idx, node_idx, inc_vals, m1n, NI / 2);

    // out = sigm(x0 + m1n) @ W_out + b_out
    gemm_out<<<(NN + 31) / 32, 256>>>(x0, m1n, W_out, b_out, out, NN);
}